// round 15
// baseline (speedup 1.0000x reference)
#include <cuda_runtime.h>
#include <cuda_fp16.h>
#include <stdint.h>

// CIN via mma.sync (HMMA): z[(b,d),s] = sum_{h,k} x0*xk*W.
// CTA: 256 threads = 8 warps, 8 batches. warp = (wy: 32 s) x (wx: 4 batches).
// 117 chunks (layer, h); layer-0 weights symmetry-folded upper-triangle.
// PER-WARP W staging: each warp cp.asyncs only its own 32 s-rows (4KB slice,
// double-buffered) and syncs with its own wait_group + syncwarp -> NO CTA
// barrier in the chunk loop; warps free-run. CTA barriers only at epilogues.

#define THREADS 256
#define NCHUNK 117
#define SW128(o) ((o) ^ ((((uint32_t)(o)) >> 3) & 0x70))

// Pre-swizzled f16 W tiles: [chunk][128 s x 64 k] = 16KB each.
__device__ __half WPREP[NCHUNK][8192];

// dynamic smem layout (bytes)
#define OFF_W    0            // 8 warps x 2 bufs x 4096B = 65536
#define OFF_XKT  65536        // 8 b x 16 d x 68 f16 = 17408  (row stride 136B)
#define OFF_X0   82944        // 8 b x 16 d x 44 u32 (f16x2 dup) = 22528
#define OFF_BIAS 105472       // 384 f32 = 1536
#define SMEM_TOTAL 107008
#define XKT_B 1088            // f16 per batch (16*68)
#define X0_B 704              // u32 per batch (16*44)

// logical k (0..63) -> physical f16 position within a 64-slot row.
// u32 index = t*8 + ks*2 + r; per (row, ks) a lane's {b0,b1} pair is one lds64
// at byte t*32 + ks*8.
__host__ __device__ __forceinline__ int pos64(int k) {
    return ((k & 6) << 3) | ((k >> 2) & 12) | ((k >> 2) & 2) | (k & 1);
}

__device__ __forceinline__ uint32_t smem_u32(const void* p) {
    uint32_t a;
    asm("{ .reg .u64 t; cvta.to.shared.u64 t, %1; cvt.u32.u64 %0, t; }" : "=r"(a) : "l"(p));
    return a;
}
__device__ __forceinline__ uint32_t hmul2(uint32_t a, uint32_t b) {
    uint32_t r;
    asm("mul.rn.f16x2 %0, %1, %2;" : "=r"(r) : "r"(a), "r"(b));
    return r;
}
__device__ __forceinline__ void lds64(uint32_t& r0, uint32_t& r1, uint32_t addr) {
    asm volatile("ld.shared.v2.b32 {%0,%1}, [%2];" : "=r"(r0), "=r"(r1) : "r"(addr));
}
__device__ __forceinline__ uint32_t lds32(uint32_t addr) {
    uint32_t r;
    asm volatile("ld.shared.b32 %0, [%1];" : "=r"(r) : "r"(addr));
    return r;
}
__device__ __forceinline__ void ldsm4(uint32_t* a, uint32_t addr) {
    asm volatile("ldmatrix.sync.aligned.m8n8.x4.shared.b16 {%0,%1,%2,%3}, [%4];"
                 : "=r"(a[0]), "=r"(a[1]), "=r"(a[2]), "=r"(a[3]) : "r"(addr));
}
__device__ __forceinline__ void mma16816(float* c, const uint32_t* a, uint32_t b0, uint32_t b1) {
    asm volatile(
        "mma.sync.aligned.m16n8k16.row.col.f32.f16.f16.f32 "
        "{%0,%1,%2,%3}, {%4,%5,%6,%7}, {%8,%9}, {%0,%1,%2,%3};"
        : "+f"(c[0]), "+f"(c[1]), "+f"(c[2]), "+f"(c[3])
        : "r"(a[0]), "r"(a[1]), "r"(a[2]), "r"(a[3]), "r"(b0), "r"(b1));
}
__device__ __forceinline__ void cp16(uint32_t dst, const void* src) {
    asm volatile("cp.async.ca.shared.global [%0], [%1], 16;" :: "r"(dst), "l"(src) : "memory");
}
__device__ __forceinline__ void cp_commit() {
    asm volatile("cp.async.commit_group;" ::: "memory");
}
template <int N>
__device__ __forceinline__ void cp_wait() {
    asm volatile("cp.async.wait_group %0;" :: "n"(N) : "memory");
}

// ---------------------------------------------------------------------------
// prep: W fp32 [h][k][s] -> per-chunk pre-swizzled f16 smem images.
// Layer 0 symmetry-folded: Wf[h][k] = W[h][k]+W[k][h] (k>h), W[h][h], else 0.
// ---------------------------------------------------------------------------
__global__ void __launch_bounds__(256) prep_w(const float* __restrict__ w0,
                                              const float* __restrict__ w1,
                                              const float* __restrict__ w2) {
    int idx = blockIdx.x * 256 + threadIdx.x;
    if (idx >= NCHUNK * 8192) return;
    int g = idx >> 13;
    int i = idx & 8191;
    int L = g / 39, h = g % 39;
    uint32_t o = SW128((uint32_t)(i * 2));   // involution
    int s = o >> 7;
    int k = (o & 127) >> 1;
    float v = 0.f;
    if (L == 0) {
        if (k < 39 && k >= h) {
            v = w0[(h * 39 + k) * 128 + s];
            if (k > h) v += w0[(k * 39 + h) * 128 + s];
        }
    } else if (L == 1) {
        v = w1[(h * 64 + k) * 128 + s];
    } else {
        v = w2[(h * 64 + k) * 128 + s];
    }
    WPREP[g][i] = __float2half_rn(v);
}

// ---------------------------------------------------------------------------
// main fused kernel
// ---------------------------------------------------------------------------
__global__ void __launch_bounds__(THREADS, 2)
cin_hmma(const float* __restrict__ inputs,
         const float* __restrict__ pb0, const float* __restrict__ pb1,
         const float* __restrict__ pb2, float* __restrict__ out) {
    extern __shared__ char smem[];
    const uint32_t sb = smem_u32(smem);
    const int tid = threadIdx.x;
    const int lane = tid & 31;
    const int wid = tid >> 5;
    const int wy = wid >> 1;          // s-group: s in [wy*32, wy*32+32)
    const int wx = wid & 1;           // batch-group: local batches wx*4..wx*4+3
    const int gid = lane >> 2;        // 0..7  (d row / B n index)
    const int tig = lane & 3;         // 0..3
    const int bstart = blockIdx.x * 8;

    __half* xkt = (__half*)(smem + OFF_XKT);
    uint32_t* x0d = (uint32_t*)(smem + OFF_X0);
    float* sbias = (float*)(smem + OFF_BIAS);

    // per-warp W slice buffers (double-buffered 4KB each)
    const uint32_t wslice = sb + OFF_W + wid * 8192;

    // prefetch chunk 0 slice into per-warp buf 0 (lane copies 128B)
    {
        const __half* src = &WPREP[0][wy * 2048 + lane * 64];
        uint32_t dst = wslice + lane * 128;
#pragma unroll
        for (int j = 0; j < 8; ++j) cp16(dst + j * 16, src + j * 8);
        cp_commit();
    }

    // zero xkt (covers layer-0 k pad + stride pad), then fill
    for (int i = tid; i < 4352; i += THREADS) ((uint32_t*)xkt)[i] = 0u;
    __syncthreads();
    for (int i = tid; i < 8 * 624; i += THREADS) {
        int b = i / 624, r = i % 624, h = r / 16, d = r % 16;
        float v = inputs[(size_t)(bstart + b) * 624 + r];
        uint16_t hb = __half_as_ushort(__float2half_rn(v));
        x0d[b * X0_B + d * 44 + h] = (uint32_t)hb * 0x10001u;
        xkt[b * XKT_B + d * 68 + pos64(h)] = __ushort_as_half(hb);
    }
    for (int i = tid; i < 384; i += THREADS)
        sbias[i] = (i < 128) ? pb0[i] : ((i < 256) ? pb1[i - 128] : pb2[i - 256]);
    __syncthreads();   // fills complete before chunk 0 work

    float C[4][2][2][4];
#pragma unroll
    for (int b = 0; b < 4; ++b)
#pragma unroll
        for (int m = 0; m < 2; ++m)
#pragma unroll
            for (int n = 0; n < 2; ++n)
#pragma unroll
                for (int j = 0; j < 4; ++j) C[b][m][n][j] = 0.f;

    // ldmatrix lane geometry (rows local to the warp's 32-row slice)
    const int rowin = (lane & 7) + ((lane >> 3) & 1) * 8;   // 0..15
    const int lcol = ((lane >> 4) & 1) * 16;

    // B lane address: bank word = (2*gid + 8*tig) mod 32 -> conflict-free halves
    const uint32_t xk_lane = (uint32_t)(gid * 136 + tig * 32);
    const uint32_t xkt_base = sb + OFF_XKT + wx * 4 * 2176;   // batch stride 2176B
    const uint32_t x0_base = sb + OFF_X0 + wx * 4 * 2816;     // batch stride 2816B

    int g = 0;
    for (int L = 0; L < 3; ++L) {
        for (int c = 0; c < 39; ++c, ++g) {
            // per-warp prefetch of next chunk's slice into the other buffer
            if (g + 1 < NCHUNK) {
                const __half* src = &WPREP[g + 1][wy * 2048 + lane * 64];
                uint32_t dst = wslice + ((g + 1) & 1) * 4096 + lane * 128;
#pragma unroll
                for (int j = 0; j < 8; ++j) cp16(dst + j * 16, src + j * 8);
            }
            cp_commit();

            // x0 f16x2 dups for h = c (layer-stable smem, no sync needed)
            uint32_t x0lo[4], x0hi[4];
#pragma unroll
            for (int bb = 0; bb < 4; ++bb) {
                uint32_t xa = x0_base + (bb * X0_B + gid * 44 + c) * 4;
                x0lo[bb] = lds32(xa);
                x0hi[bb] = lds32(xa + 1408);
            }

            cp_wait<1>();      // this warp's chunk-g slice resident
            __syncwarp();

            const uint32_t wbase = wslice + (g & 1) * 4096;

            // layer 0 (folded upper triangle): valid k-slabs [c>>4 .. 2];
            // layers 1/2: [0 .. 3].
            const int klo = (L == 0) ? (c >> 4) : 0;
            const int khi = (L == 0) ? 2 : 3;

            for (int ks = klo; ks <= khi; ++ks) {
                uint32_t A0[4], A1[4];
                ldsm4(A0, wbase + SW128((uint32_t)(rowin * 128 + ks * 32 + lcol)));
                ldsm4(A1, wbase + SW128((uint32_t)((rowin + 16) * 128 + ks * 32 + lcol)));
                const uint32_t kbyte = (uint32_t)(ks * 8);
#pragma unroll
                for (int bb = 0; bb < 4; ++bb) {
                    uint32_t xb = xkt_base + bb * 2176 + xk_lane + kbyte;
                    uint32_t rx, ry, qx, qy;
                    lds64(rx, ry, xb);
                    lds64(qx, qy, xb + 1088);
                    uint32_t b00 = hmul2(rx, x0lo[bb]);
                    uint32_t b01 = hmul2(ry, x0lo[bb]);
                    uint32_t b10 = hmul2(qx, x0hi[bb]);
                    uint32_t b11 = hmul2(qy, x0hi[bb]);
                    mma16816(C[bb][0][0], A0, b00, b01);
                    mma16816(C[bb][0][1], A0, b10, b11);
                    mma16816(C[bb][1][0], A1, b00, b01);
                    mma16816(C[bb][1][1], A1, b10, b11);
                }
            }
            // no CTA barrier: W slice is private, xkt read-only within layer
        }

        __syncthreads();   // all warps' MMA reads of xkt done before overwrite

        // ---- layer epilogue ----
#pragma unroll
        for (int bb = 0; bb < 4; ++bb) {
            float* outp = out + (size_t)(bstart + wx * 4 + bb) * 256;
            __half* xkb = xkt + (wx * 4 + bb) * XKT_B;
#pragma unroll
            for (int m = 0; m < 2; ++m) {
                const int s_r = wy * 32 + m * 16 + gid;      // and s_r + 8
                const float b_r = sbias[L * 128 + s_r];
                const float b_r8 = sbias[L * 128 + s_r + 8];
                float vr = 0.f, vr8 = 0.f;
                const int pos = pos64(s_r & 63);
                const int pos8 = pos64((s_r + 8) & 63);
#pragma unroll
                for (int n = 0; n < 2; ++n)
#pragma unroll
                    for (int j = 0; j < 2; ++j) {
                        const int d = 2 * tig + j + n * 8;
                        float z = fmaxf(C[bb][m][n][j] + b_r, 0.f);
                        float z8 = fmaxf(C[bb][m][n][2 + j] + b_r8, 0.f);
                        if (L < 2 && wy < 2) {
                            xkb[d * 68 + pos] = __float2half_rn(z);
                            xkb[d * 68 + pos8] = __float2half_rn(z8);
                        }
                        vr += z;
                        vr8 += z8;
                    }
                vr += __shfl_xor_sync(0xffffffffu, vr, 1);
                vr += __shfl_xor_sync(0xffffffffu, vr, 2);
                vr8 += __shfl_xor_sync(0xffffffffu, vr8, 1);
                vr8 += __shfl_xor_sync(0xffffffffu, vr8, 2);
                if (tig == 0) {
                    if (L == 2) {
                        outp[128 + s_r] = vr;
                        outp[128 + s_r + 8] = vr8;
                    } else if (wy >= 2) {
                        outp[L * 64 + s_r - 64] = vr;
                        outp[L * 64 + s_r - 64 + 8] = vr8;
                    }
                }
            }
#pragma unroll
            for (int m = 0; m < 2; ++m)
#pragma unroll
                for (int n = 0; n < 2; ++n)
#pragma unroll
                    for (int j = 0; j < 4; ++j) C[bb][m][n][j] = 0.f;
        }
        __syncthreads();   // new xkt visible before next layer
    }
}

extern "C" void kernel_launch(void* const* d_in, const int* in_sizes, int n_in,
                              void* d_out, int out_size) {
    const float *inp = nullptr, *w0 = nullptr, *w1 = nullptr, *w2 = nullptr;
    const float *pb0 = nullptr, *pb1 = nullptr, *pb2 = nullptr;
    for (int i = 0; i < n_in; ++i) {
        const float* p = (const float*)d_in[i];
        int s = in_sizes[i];
        if (s == 2048 * 39 * 16) {
            inp = p;
        } else if (s == 39 * 39 * 128) {
            w0 = p;
        } else if (s == 39 * 64 * 128) {
            if (!w1) w1 = p; else w2 = p;
        } else if (s == 128) {
            if (!pb0) pb0 = p; else if (!pb1) pb1 = p; else pb2 = p;
        }
    }
    cudaFuncSetAttribute(cin_hmma, cudaFuncAttributeMaxDynamicSharedMemorySize, SMEM_TOTAL);
    prep_w<<<(NCHUNK * 8192 + 255) / 256, 256>>>(w0, w1, w2);
    cin_hmma<<<256, THREADS, SMEM_TOTAL>>>(inp, pb0, pb1, pb2, (float*)d_out);
}

// round 16
// speedup vs baseline: 1.9105x; 1.9105x over previous
#include <cuda_runtime.h>
#include <cuda_fp16.h>
#include <stdint.h>

// CIN via mma.sync (HMMA): z[(b,d),s] = sum_{h,k} x0*xk*W.
// CTA: 256 threads = 8 warps, 8 batches. warp = (wy: 32 s) x (wx: 4 batches).
// 117 chunks (layer, h); layer-0 weights symmetry-folded upper-triangle so
// chunk h runs ks-slabs [h>>4 .. 2]; layers 1/2 run [0..3].
// W staged PER PAIR (the two wx-warps sharing one 32-s-row slice): 4KB slice,
// triple-buffered, named barrier bar.sync(1+wy, 64) -- no CTA-wide barrier in
// the chunk loop. Same total LDGSTS as CTA staging (no duplication).

#define THREADS 256
#define NCHUNK 117
#define SW128(o) ((o) ^ ((((uint32_t)(o)) >> 3) & 0x70))

// Pre-swizzled f16 W tiles: [chunk][128 s x 64 k] = 16KB each.
__device__ __half WPREP[NCHUNK][8192];

// dynamic smem layout (bytes)
#define OFF_W    0            // 4 pairs x 3 bufs x 4096B = 49152
#define OFF_XKT  49152        // 8 b x 16 d x 68 f16 = 17408  (row stride 136B)
#define OFF_X0   66560        // 8 b x 16 d x 44 u32 (f16x2 dup) = 22528
#define OFF_BIAS 89088        // 384 f32 = 1536
#define SMEM_TOTAL 90624
#define XKT_B 1088            // f16 per batch (16*68)
#define X0_B 704              // u32 per batch (16*44)

// logical k (0..63) -> physical f16 position within a 64-slot row.
// u32 index = t*8 + ks*2 + r; per (row, ks) a lane's {b0,b1} pair is one lds64
// at byte t*32 + ks*8. Bank word = (2*gid + 8*tig) mod 32 -> conflict-free.
__host__ __device__ __forceinline__ int pos64(int k) {
    return ((k & 6) << 3) | ((k >> 2) & 12) | ((k >> 2) & 2) | (k & 1);
}

__device__ __forceinline__ uint32_t smem_u32(const void* p) {
    uint32_t a;
    asm("{ .reg .u64 t; cvta.to.shared.u64 t, %1; cvt.u32.u64 %0, t; }" : "=r"(a) : "l"(p));
    return a;
}
__device__ __forceinline__ uint32_t hmul2(uint32_t a, uint32_t b) {
    uint32_t r;
    asm("mul.rn.f16x2 %0, %1, %2;" : "=r"(r) : "r"(a), "r"(b));
    return r;
}
__device__ __forceinline__ void lds64(uint32_t& r0, uint32_t& r1, uint32_t addr) {
    asm volatile("ld.shared.v2.b32 {%0,%1}, [%2];" : "=r"(r0), "=r"(r1) : "r"(addr));
}
__device__ __forceinline__ uint32_t lds32(uint32_t addr) {
    uint32_t r;
    asm volatile("ld.shared.b32 %0, [%1];" : "=r"(r) : "r"(addr));
    return r;
}
__device__ __forceinline__ void ldsm4(uint32_t* a, uint32_t addr) {
    asm volatile("ldmatrix.sync.aligned.m8n8.x4.shared.b16 {%0,%1,%2,%3}, [%4];"
                 : "=r"(a[0]), "=r"(a[1]), "=r"(a[2]), "=r"(a[3]) : "r"(addr));
}
__device__ __forceinline__ void mma16816(float* c, const uint32_t* a, uint32_t b0, uint32_t b1) {
    asm volatile(
        "mma.sync.aligned.m16n8k16.row.col.f32.f16.f16.f32 "
        "{%0,%1,%2,%3}, {%4,%5,%6,%7}, {%8,%9}, {%0,%1,%2,%3};"
        : "+f"(c[0]), "+f"(c[1]), "+f"(c[2]), "+f"(c[3])
        : "r"(a[0]), "r"(a[1]), "r"(a[2]), "r"(a[3]), "r"(b0), "r"(b1));
}
__device__ __forceinline__ void cp16(uint32_t dst, const void* src) {
    asm volatile("cp.async.ca.shared.global [%0], [%1], 16;" :: "r"(dst), "l"(src) : "memory");
}
__device__ __forceinline__ void cp_commit() {
    asm volatile("cp.async.commit_group;" ::: "memory");
}
template <int N>
__device__ __forceinline__ void cp_wait() {
    asm volatile("cp.async.wait_group %0;" :: "n"(N) : "memory");
}
__device__ __forceinline__ void bar_pair(int id) {
    asm volatile("bar.sync %0, 64;" :: "r"(id) : "memory");
}

// ---------------------------------------------------------------------------
// prep: W fp32 [h][k][s] -> per-chunk pre-swizzled f16 smem images.
// Layer 0 symmetry-folded: Wf[h][k] = W[h][k]+W[k][h] (k>h), W[h][h], else 0.
// ---------------------------------------------------------------------------
__global__ void __launch_bounds__(256) prep_w(const float* __restrict__ w0,
                                              const float* __restrict__ w1,
                                              const float* __restrict__ w2) {
    int idx = blockIdx.x * 256 + threadIdx.x;
    if (idx >= NCHUNK * 8192) return;
    int g = idx >> 13;
    int i = idx & 8191;
    int L = g / 39, h = g % 39;
    uint32_t o = SW128((uint32_t)(i * 2));   // involution
    int s = o >> 7;
    int k = (o & 127) >> 1;
    float v = 0.f;
    if (L == 0) {
        if (k < 39 && k >= h) {
            v = w0[(h * 39 + k) * 128 + s];
            if (k > h) v += w0[(k * 39 + h) * 128 + s];
        }
    } else if (L == 1) {
        v = w1[(h * 64 + k) * 128 + s];
    } else {
        v = w2[(h * 64 + k) * 128 + s];
    }
    WPREP[g][i] = __float2half_rn(v);
}

// ---------------------------------------------------------------------------
// main fused kernel
// ---------------------------------------------------------------------------
__global__ void __launch_bounds__(THREADS, 2)
cin_hmma(const float* __restrict__ inputs,
         const float* __restrict__ pb0, const float* __restrict__ pb1,
         const float* __restrict__ pb2, float* __restrict__ out) {
    extern __shared__ char smem[];
    const uint32_t sb = smem_u32(smem);
    const int tid = threadIdx.x;
    const int lane = tid & 31;
    const int wid = tid >> 5;
    const int wy = wid >> 1;          // s-group (pair id): s in [wy*32, wy*32+32)
    const int wx = wid & 1;           // batch-group: local batches wx*4..wx*4+3
    const int gid = lane >> 2;        // 0..7  (d row / B n index)
    const int tig = lane & 3;         // 0..3
    const int t64 = tid & 63;         // thread index within the pair
    const int bstart = blockIdx.x * 8;

    __half* xkt = (__half*)(smem + OFF_XKT);
    uint32_t* x0d = (uint32_t*)(smem + OFF_X0);
    float* sbias = (float*)(smem + OFF_BIAS);

    // per-pair W slice buffers: 3 x 4KB
    const uint32_t pairbase = sb + OFF_W + wy * 12288;

    // prefetch chunk 0 slice into pair buf 0 (thread copies 64B)
    {
        const __half* src = &WPREP[0][wy * 2048 + t64 * 32];
        uint32_t dst = pairbase + t64 * 64;
#pragma unroll
        for (int j = 0; j < 4; ++j) cp16(dst + j * 16, src + j * 8);
        cp_commit();
    }

    // zero xkt (covers layer-0 k pad + stride pad), then fill
    for (int i = tid; i < 4352; i += THREADS) ((uint32_t*)xkt)[i] = 0u;
    __syncthreads();
    for (int i = tid; i < 8 * 624; i += THREADS) {
        int b = i / 624, r = i % 624, h = r / 16, d = r % 16;
        float v = inputs[(size_t)(bstart + b) * 624 + r];
        uint16_t hb = __half_as_ushort(__float2half_rn(v));
        x0d[b * X0_B + d * 44 + h] = (uint32_t)hb * 0x10001u;
        xkt[b * XKT_B + d * 68 + pos64(h)] = __ushort_as_half(hb);
    }
    for (int i = tid; i < 384; i += THREADS)
        sbias[i] = (i < 128) ? pb0[i] : ((i < 256) ? pb1[i - 128] : pb2[i - 256]);
    __syncthreads();   // fills complete before chunk 0 work

    float C[4][2][2][4];
#pragma unroll
    for (int b = 0; b < 4; ++b)
#pragma unroll
        for (int m = 0; m < 2; ++m)
#pragma unroll
            for (int n = 0; n < 2; ++n)
#pragma unroll
                for (int j = 0; j < 4; ++j) C[b][m][n][j] = 0.f;

    // ldmatrix lane geometry (rows local to the pair's 32-row slice)
    const int rowin = (lane & 7) + ((lane >> 3) & 1) * 8;   // 0..15
    const int lcol = ((lane >> 4) & 1) * 16;

    // B lane address: bank word = (2*gid + 8*tig) mod 32 -> conflict-free halves
    const uint32_t xk_lane = (uint32_t)(gid * 136 + tig * 32);
    const uint32_t xkt_base = sb + OFF_XKT + wx * 4 * 2176;   // batch stride 2176B
    const uint32_t x0_base = sb + OFF_X0 + wx * 4 * 2816;     // batch stride 2816B

    int g = 0, buf = 0;
    for (int L = 0; L < 3; ++L) {
        for (int c = 0; c < 39; ++c, ++g) {
            int nbuf = buf + 1;
            if (nbuf == 3) nbuf = 0;
            // per-pair prefetch of next chunk's slice (no duplication)
            if (g + 1 < NCHUNK) {
                const __half* src = &WPREP[g + 1][wy * 2048 + t64 * 32];
                uint32_t dst = pairbase + nbuf * 4096 + t64 * 64;
#pragma unroll
                for (int j = 0; j < 4; ++j) cp16(dst + j * 16, src + j * 8);
            }
            cp_commit();

            // pre-wait loads (layer-stable smem): x0 dups for h = c
            uint32_t x0lo[4], x0hi[4];
#pragma unroll
            for (int bb = 0; bb < 4; ++bb) {
                uint32_t xa = x0_base + (bb * X0_B + gid * 44 + c) * 4;
                x0lo[bb] = lds32(xa);
                x0hi[bb] = lds32(xa + 1408);
            }

            cp_wait<1>();        // this thread's chunk-g slice copies done
            bar_pair(1 + wy);    // both warps of the pair arrived -> slice ready

            const uint32_t wbase = pairbase + buf * 4096;

            // layer 0 (folded upper triangle): valid k-slabs [c>>4 .. 2];
            // layers 1/2: [0 .. 3].
            const int klo = (L == 0) ? (c >> 4) : 0;
            const int khi = (L == 0) ? 2 : 3;

            for (int ks = klo; ks <= khi; ++ks) {
                uint32_t A0[4], A1[4];
                ldsm4(A0, wbase + SW128((uint32_t)(rowin * 128 + ks * 32 + lcol)));
                ldsm4(A1, wbase + SW128((uint32_t)((rowin + 16) * 128 + ks * 32 + lcol)));
                const uint32_t kbyte = (uint32_t)(ks * 8);
#pragma unroll
                for (int bb = 0; bb < 4; ++bb) {
                    uint32_t xb = xkt_base + bb * 2176 + xk_lane + kbyte;
                    uint32_t rx, ry, qx, qy;
                    lds64(rx, ry, xb);
                    lds64(qx, qy, xb + 1088);
                    uint32_t b00 = hmul2(rx, x0lo[bb]);
                    uint32_t b01 = hmul2(ry, x0lo[bb]);
                    uint32_t b10 = hmul2(qx, x0hi[bb]);
                    uint32_t b11 = hmul2(qy, x0hi[bb]);
                    mma16816(C[bb][0][0], A0, b00, b01);
                    mma16816(C[bb][0][1], A0, b10, b11);
                    mma16816(C[bb][1][0], A1, b00, b01);
                    mma16816(C[bb][1][1], A1, b10, b11);
                }
            }
            buf = nbuf;
            // no CTA barrier: W slice is pair-private (triple-buffered),
            // xkt/x0 read-only within a layer
        }

        __syncthreads();   // all warps' MMA reads of xkt done before overwrite

        // ---- layer epilogue ----
#pragma unroll
        for (int bb = 0; bb < 4; ++bb) {
            float* outp = out + (size_t)(bstart + wx * 4 + bb) * 256;
            __half* xkb = xkt + (wx * 4 + bb) * XKT_B;
#pragma unroll
            for (int m = 0; m < 2; ++m) {
                const int s_r = wy * 32 + m * 16 + gid;      // and s_r + 8
                const float b_r = sbias[L * 128 + s_r];
                const float b_r8 = sbias[L * 128 + s_r + 8];
                float vr = 0.f, vr8 = 0.f;
                const int pos = pos64(s_r & 63);
                const int pos8 = pos64((s_r + 8) & 63);
#pragma unroll
                for (int n = 0; n < 2; ++n)
#pragma unroll
                    for (int j = 0; j < 2; ++j) {
                        const int d = 2 * tig + j + n * 8;
                        float z = fmaxf(C[bb][m][n][j] + b_r, 0.f);
                        float z8 = fmaxf(C[bb][m][n][2 + j] + b_r8, 0.f);
                        if (L < 2 && wy < 2) {
                            xkb[d * 68 + pos] = __float2half_rn(z);
                            xkb[d * 68 + pos8] = __float2half_rn(z8);
                        }
                        vr += z;
                        vr8 += z8;
                    }
                vr += __shfl_xor_sync(0xffffffffu, vr, 1);
                vr += __shfl_xor_sync(0xffffffffu, vr, 2);
                vr8 += __shfl_xor_sync(0xffffffffu, vr8, 1);
                vr8 += __shfl_xor_sync(0xffffffffu, vr8, 2);
                if (tig == 0) {
                    if (L == 2) {
                        outp[128 + s_r] = vr;
                        outp[128 + s_r + 8] = vr8;
                    } else if (wy >= 2) {
                        outp[L * 64 + s_r - 64] = vr;
                        outp[L * 64 + s_r - 64 + 8] = vr8;
                    }
                }
            }
#pragma unroll
            for (int m = 0; m < 2; ++m)
#pragma unroll
                for (int n = 0; n < 2; ++n)
#pragma unroll
                    for (int j = 0; j < 4; ++j) C[bb][m][n][j] = 0.f;
        }
        __syncthreads();   // new xkt visible before next layer
    }
}

extern "C" void kernel_launch(void* const* d_in, const int* in_sizes, int n_in,
                              void* d_out, int out_size) {
    const float *inp = nullptr, *w0 = nullptr, *w1 = nullptr, *w2 = nullptr;
    const float *pb0 = nullptr, *pb1 = nullptr, *pb2 = nullptr;
    for (int i = 0; i < n_in; ++i) {
        const float* p = (const float*)d_in[i];
        int s = in_sizes[i];
        if (s == 2048 * 39 * 16) {
            inp = p;
        } else if (s == 39 * 39 * 128) {
            w0 = p;
        } else if (s == 39 * 64 * 128) {
            if (!w1) w1 = p; else w2 = p;
        } else if (s == 128) {
            if (!pb0) pb0 = p; else if (!pb1) pb1 = p; else pb2 = p;
        }
    }
    cudaFuncSetAttribute(cin_hmma, cudaFuncAttributeMaxDynamicSharedMemorySize, SMEM_TOTAL);
    prep_w<<<(NCHUNK * 8192 + 255) / 256, 256>>>(w0, w1, w2);
    cin_hmma<<<256, THREADS, SMEM_TOTAL>>>(inp, pb0, pb1, pb2, (float*)d_out);
}